// round 1
// baseline (speedup 1.0000x reference)
#include <cuda_runtime.h>

// Problem constants
#define BB     64
#define LL     512
#define NCH    64
#define AA     64
#define DD     256
#define PP     16
#define SBASE  8
#define MAXOFF 4.0f

#define NCHUNK 8
#define LCHUNK 64   // LL / NCHUNK

// Partial pooled sums: [b][chunk][32]  (deterministic, no atomics)
__device__ float g_part[BB * NCHUNK * 32];

// ---------------------------------------------------------------------------
// packed f32x2 helpers (sm_100a)
// ---------------------------------------------------------------------------
__device__ __forceinline__ unsigned long long pack2(float lo, float hi) {
    unsigned long long r;
    asm("mov.b64 %0, {%1, %2};" : "=l"(r) : "f"(lo), "f"(hi));
    return r;
}
__device__ __forceinline__ float2 unpack2(unsigned long long v) {
    float2 r;
    asm("mov.b64 {%0, %1}, %2;" : "=f"(r.x), "=f"(r.y) : "l"(v));
    return r;
}
__device__ __forceinline__ unsigned long long fma2(unsigned long long a,
                                                   unsigned long long b,
                                                   unsigned long long c) {
    unsigned long long d;
    asm("fma.rn.f32x2 %0, %1, %2, %3;" : "=l"(d) : "l"(a), "l"(b), "l"(c));
    return d;
}

// ---------------------------------------------------------------------------
// Kernel 1: conv1d(N->32,k=3,pad=1) + ReLU + partial mean-pool
// grid: (NCHUNK, B), block: 128 threads = 8 o-groups x 16 l-groups
// Each thread: 4 o x 4 l register tile over 64 l's of one chunk.
// ---------------------------------------------------------------------------
__global__ __launch_bounds__(128) void k_convpool(
    const float* __restrict__ x,       // (B, L, N)
    const float* __restrict__ conv_w,  // (32, N, 3)
    const float* __restrict__ conv_b)  // (32)
{
    const int c = blockIdx.x, b = blockIdx.y;
    const int tid = threadIdx.x;
    const int og = tid & 7;      // 0..7  -> o0 = og*4
    const int lg = tid >> 3;     // 0..15 -> l-base = lg*4
    const int o0 = og * 4;

    __shared__ float sx[66 * 65];       // rows L0-1 .. L0+64, pitch 65 (odd-ish)
    __shared__ float sw[32 * 193];      // conv_w, per-o pitch 193
    __shared__ float sred[32][17];      // [o][lg]

    const int L0 = c * LCHUNK;

    // load x slab (66 rows x 64 ch), zero-padded at borders
    for (int i = tid; i < 66 * 64; i += 128) {
        int r = i >> 6, n = i & 63;
        int gl = L0 - 1 + r;
        float v = 0.f;
        if (gl >= 0 && gl < LL) v = x[(b * LL + gl) * NCH + n];
        sx[r * 65 + n] = v;
    }
    // load conv weights
    for (int i = tid; i < 32 * 192; i += 128) {
        int o = i / 192, rem = i - o * 192;
        sw[o * 193 + rem] = conv_w[i];
    }
    __syncthreads();

    float acc[4][4];
#pragma unroll
    for (int o = 0; o < 4; o++)
#pragma unroll
        for (int dl = 0; dl < 4; dl++) acc[o][dl] = 0.f;

    const int lbase = lg * 4;
    for (int n = 0; n < 64; n++) {
        float xv[6];
#pragma unroll
        for (int j = 0; j < 6; j++) xv[j] = sx[(lbase + j) * 65 + n];
#pragma unroll
        for (int o = 0; o < 4; o++) {
            const float* wp = &sw[(o0 + o) * 193 + n * 3];
            float w0 = wp[0], w1 = wp[1], w2 = wp[2];
#pragma unroll
            for (int dl = 0; dl < 4; dl++)
                acc[o][dl] += xv[dl] * w0 + xv[dl + 1] * w1 + xv[dl + 2] * w2;
        }
    }

    // bias + ReLU + sum over this thread's 4 l's
#pragma unroll
    for (int o = 0; o < 4; o++) {
        float cb = conv_b[o0 + o];
        float s = 0.f;
#pragma unroll
        for (int dl = 0; dl < 4; dl++) s += fmaxf(acc[o][dl] + cb, 0.f);
        sred[o0 + o][lg] = s;
    }
    __syncthreads();

    if (tid < 32) {
        float s = 0.f;
#pragma unroll
        for (int j = 0; j < 16; j++) s += sred[tid][j];
        g_part[(b * NCHUNK + c) * 32 + tid] = s;
    }
}

// ---------------------------------------------------------------------------
// Kernel 2: delta -> bilinear gather -> patch projection (P->D) -> out
// grid: B*A blocks (blockIdx.x = b*64 + a), 256 threads.
// Phase 1: warp 0 computes delta[b][a] + sample indices/fractions.
// Phase 2: build samp[n][p] in SMEM (pitch 20 floats, conflict-free 128b ops).
// Phase 3: each thread -> 4 consecutive d, loops n; f32x2 packed FMAs.
// ---------------------------------------------------------------------------
__global__ __launch_bounds__(256) void k_main(
    const float* __restrict__ x,      // (B, L, N)
    const float* __restrict__ lin_w,  // (A, 32)
    const float* __restrict__ lin_b,  // (A)
    const float* __restrict__ wp_w,   // (D, P)
    const float* __restrict__ wp_b,   // (D)
    float* __restrict__ out)          // (B*N, A, D)
{
    const int bx = blockIdx.x;
    const int b = bx >> 6, a = bx & 63;
    const int tid = threadIdx.x;

    __shared__ float samp[64 * 20];   // [n][p], pitch 20 floats (80B)
    __shared__ int   si0[PP];
    __shared__ int   si1[PP];
    __shared__ float sf[PP];

    // ---- Phase 1: delta + sampling params (warp 0) ----
    if (tid < 32) {
        float v = 0.f;
#pragma unroll
        for (int c = 0; c < NCHUNK; c++)
            v += g_part[(b * NCHUNK + c) * 32 + tid];
        v *= (1.0f / (float)LL);
        v *= lin_w[a * 32 + tid];
#pragma unroll
        for (int off = 16; off; off >>= 1)
            v += __shfl_xor_sync(0xffffffffu, v, off);
        float deltav = MAXOFF * tanhf(v + lin_b[a]);
        if (tid < PP) {
            float xs = (float)(a * SBASE) + deltav + ((float)tid - 7.5f);
            xs = fminf(fmaxf(xs, 0.0f), (float)(LL - 1));
            float fl = floorf(xs);
            int i0 = (int)fl;
            float f = xs - fl;
            int i1 = min(i0 + 1, LL - 1);
            si0[tid] = i0;
            si1[tid] = i1;
            sf[tid]  = f;
        }
    }
    __syncthreads();

    // ---- Phase 2: bilinear gather into SMEM ----
    {
        const int n = tid & 63, pg = tid >> 6;   // pg in 0..3, 4 p's each
        const float* xb = x + (size_t)b * (LL * NCH) + n;
        float tmp[4];
#pragma unroll
        for (int j = 0; j < 4; j++) {
            int p = pg * 4 + j;
            float g0 = xb[(size_t)si0[p] * NCH];
            float g1 = xb[(size_t)si1[p] * NCH];
            tmp[j] = fmaf(sf[p], g1 - g0, g0);   // g0*(1-f)+g1*f
        }
        *(float4*)&samp[n * 20 + pg * 4] =
            make_float4(tmp[0], tmp[1], tmp[2], tmp[3]);
    }
    __syncthreads();

    // ---- Phase 3: patch projection, f32x2 packed over p-pairs ----
    const int dq = tid & 63, ng = tid >> 6;
    const int d0 = dq * 4;

    unsigned long long w2[4][8];
    float wb[4];
#pragma unroll
    for (int d = 0; d < 4; d++) {
        wb[d] = wp_b[d0 + d];
#pragma unroll
        for (int pp = 0; pp < 8; pp++)
            w2[d][pp] = pack2(wp_w[(d0 + d) * PP + 2 * pp],
                              wp_w[(d0 + d) * PP + 2 * pp + 1]);
    }

    float* outb = out + ((size_t)(b * 64) * 64 + a) * 256 + d0;

    for (int n = ng; n < 64; n += 4) {
        const ulonglong2* sv = (const ulonglong2*)&samp[n * 20];
        ulonglong2 v0 = sv[0], v1 = sv[1], v2 = sv[2], v3 = sv[3];
        unsigned long long sp[8] = {v0.x, v0.y, v1.x, v1.y,
                                    v2.x, v2.y, v3.x, v3.y};
        float rr[4];
#pragma unroll
        for (int d = 0; d < 4; d++) {
            unsigned long long acc = 0ull;       // = {+0.f, +0.f}
#pragma unroll
            for (int q = 0; q < 8; q++)
                acc = fma2(sp[q], w2[d][q], acc);
            float2 ac = unpack2(acc);
            rr[d] = ac.x + ac.y + wb[d];
        }
        *(float4*)&outb[(size_t)n * (64 * 256)] =
            make_float4(rr[0], rr[1], rr[2], rr[3]);
    }
}

// ---------------------------------------------------------------------------
extern "C" void kernel_launch(void* const* d_in, const int* in_sizes, int n_in,
                              void* d_out, int out_size)
{
    const float* x      = (const float*)d_in[0];
    const float* conv_w = (const float*)d_in[1];
    const float* conv_b = (const float*)d_in[2];
    const float* lin_w  = (const float*)d_in[3];
    const float* lin_b  = (const float*)d_in[4];
    const float* wp_w   = (const float*)d_in[5];
    const float* wp_b   = (const float*)d_in[6];
    float* out = (float*)d_out;

    k_convpool<<<dim3(NCHUNK, BB), 128>>>(x, conv_w, conv_b);
    k_main<<<BB * AA, 256>>>(x, lin_w, lin_b, wp_w, wp_b, out);
}

// round 3
// speedup vs baseline: 2.6776x; 2.6776x over previous
#include <cuda_runtime.h>

// Problem constants
#define BB     64
#define LL     512
#define NCH    64
#define AA     64
#define DD     256
#define PP     16
#define SBASE  8
#define MAXOFF 4.0f

#define NCHUNK 8
#define LCHUNK 64   // LL / NCHUNK

// Partial pooled sums: [b][chunk][32]  (deterministic, no atomics)
__device__ float g_part[BB * NCHUNK * 32];
// Sampling params per (b,a,p)
__device__ int   g_i0[BB * AA * PP];
__device__ float g_f [BB * AA * PP];

// ---------------------------------------------------------------------------
// packed f32x2 helpers (sm_100a)
// ---------------------------------------------------------------------------
__device__ __forceinline__ unsigned long long pack2(float lo, float hi) {
    unsigned long long r;
    asm("mov.b64 %0, {%1, %2};" : "=l"(r) : "f"(lo), "f"(hi));
    return r;
}
__device__ __forceinline__ float2 unpack2(unsigned long long v) {
    float2 r;
    asm("mov.b64 {%0, %1}, %2;" : "=f"(r.x), "=f"(r.y) : "l"(v));
    return r;
}
__device__ __forceinline__ unsigned long long fma2(unsigned long long a,
                                                   unsigned long long b,
                                                   unsigned long long c) {
    unsigned long long d;
    asm("fma.rn.f32x2 %0, %1, %2, %3;" : "=l"(d) : "l"(a), "l"(b), "l"(c));
    return d;
}

// ---------------------------------------------------------------------------
// Kernel 1: conv1d(N->32,k=3,pad=1) + ReLU + partial mean-pool
// grid: (NCHUNK, B), block: 128 threads = 8 o-groups x 16 l-groups
// ---------------------------------------------------------------------------
__global__ __launch_bounds__(128) void k_convpool(
    const float* __restrict__ x,       // (B, L, N)
    const float* __restrict__ conv_w,  // (32, N, 3)
    const float* __restrict__ conv_b)  // (32)
{
    const int c = blockIdx.x, b = blockIdx.y;
    const int tid = threadIdx.x;
    const int og = tid & 7;
    const int lg = tid >> 3;
    const int o0 = og * 4;

    __shared__ float sx[66 * 65];
    __shared__ float sw[32 * 193];
    __shared__ float sred[32][17];

    const int L0 = c * LCHUNK;

    for (int i = tid; i < 66 * 64; i += 128) {
        int r = i >> 6, n = i & 63;
        int gl = L0 - 1 + r;
        float v = 0.f;
        if (gl >= 0 && gl < LL) v = x[(b * LL + gl) * NCH + n];
        sx[r * 65 + n] = v;
    }
    for (int i = tid; i < 32 * 192; i += 128) {
        int o = i / 192, rem = i - o * 192;
        sw[o * 193 + rem] = conv_w[i];
    }
    __syncthreads();

    float acc[4][4];
#pragma unroll
    for (int o = 0; o < 4; o++)
#pragma unroll
        for (int dl = 0; dl < 4; dl++) acc[o][dl] = 0.f;

    const int lbase = lg * 4;
    for (int n = 0; n < 64; n++) {
        float xv[6];
#pragma unroll
        for (int j = 0; j < 6; j++) xv[j] = sx[(lbase + j) * 65 + n];
#pragma unroll
        for (int o = 0; o < 4; o++) {
            const float* wp = &sw[(o0 + o) * 193 + n * 3];
            float w0 = wp[0], w1 = wp[1], w2 = wp[2];
#pragma unroll
            for (int dl = 0; dl < 4; dl++)
                acc[o][dl] += xv[dl] * w0 + xv[dl + 1] * w1 + xv[dl + 2] * w2;
        }
    }

#pragma unroll
    for (int o = 0; o < 4; o++) {
        float cb = conv_b[o0 + o];
        float s = 0.f;
#pragma unroll
        for (int dl = 0; dl < 4; dl++) s += fmaxf(acc[o][dl] + cb, 0.f);
        sred[o0 + o][lg] = s;
    }
    __syncthreads();

    if (tid < 32) {
        float s = 0.f;
#pragma unroll
        for (int j = 0; j < 16; j++) s += sred[tid][j];
        g_part[(b * NCHUNK + c) * 32 + tid] = s;
    }
}

// ---------------------------------------------------------------------------
// Kernel 1b: delta -> per-(b,a,p) sampling indices + fractions
// grid: B, block: 64 (one thread per a)
// ---------------------------------------------------------------------------
__global__ __launch_bounds__(64) void k_delta(
    const float* __restrict__ lin_w,  // (A, 32)
    const float* __restrict__ lin_b)  // (A)
{
    const int b = blockIdx.x;
    const int a = threadIdx.x;

    __shared__ float pooled[32];
    if (a < 32) {
        float s = 0.f;
#pragma unroll
        for (int c = 0; c < NCHUNK; c++)
            s += g_part[(b * NCHUNK + c) * 32 + a];
        pooled[a] = s * (1.0f / (float)LL);
    }
    __syncthreads();

    float v = lin_b[a];
#pragma unroll
    for (int k = 0; k < 32; k++)
        v = fmaf(pooled[k], lin_w[a * 32 + k], v);
    float deltav = MAXOFF * tanhf(v);

    const int base = (b * AA + a) * PP;
#pragma unroll
    for (int p = 0; p < PP; p++) {
        float xs = (float)(a * SBASE) + deltav + ((float)p - 7.5f);
        xs = fminf(fmaxf(xs, 0.0f), (float)(LL - 1));
        float fl = floorf(xs);
        g_i0[base + p] = (int)fl;
        g_f [base + p] = xs - fl;
    }
}

// ---------------------------------------------------------------------------
// Kernel 2: bilinear gather -> patch projection (P->D) -> out
// grid: B*A blocks, 256 threads. No spills: thread owns a d-PAIR
// (16 packed weights = 32 regs), loops 32 n-iterations.
// ---------------------------------------------------------------------------
__global__ __launch_bounds__(256, 3) void k_main(
    const float* __restrict__ x,      // (B, L, N)
    const float* __restrict__ wp_w,   // (D, P)
    const float* __restrict__ wp_b,   // (D)
    float* __restrict__ out)          // (B*N, A, D)
{
    const int bx = blockIdx.x;
    const int b = bx >> 6, a = bx & 63;
    const int tid = threadIdx.x;

    __shared__ float samp[64 * 20];   // [n][p], pitch 20 floats
    __shared__ int   si0[PP];
    __shared__ float sf[PP];

    // ---- Phase A: fetch sampling params ----
    if (tid < PP) {
        si0[tid] = g_i0[(b * AA + a) * PP + tid];
        sf[tid]  = g_f [(b * AA + a) * PP + tid];
    }
    __syncthreads();

    // ---- Phase B: bilinear gather into SMEM ----
    {
        const int n = tid & 63, pg = tid >> 6;   // 4 p's each
        const float* xb = x + (size_t)b * (LL * NCH) + n;
        float tmp[4];
#pragma unroll
        for (int j = 0; j < 4; j++) {
            int p = pg * 4 + j;
            int i0 = si0[p];
            int i1 = min(i0 + 1, LL - 1);
            float g0 = xb[(size_t)i0 * NCH];
            float g1 = xb[(size_t)i1 * NCH];
            tmp[j] = fmaf(sf[p], g1 - g0, g0);
        }
        *(float4*)&samp[n * 20 + pg * 4] =
            make_float4(tmp[0], tmp[1], tmp[2], tmp[3]);
    }
    __syncthreads();

    // ---- Phase C: patch projection; thread owns d-pair, 32 n-iters ----
    const int dp = tid & 127;            // d-pair index 0..127
    const int ng = tid >> 7;             // 0..1
    const int d0 = dp * 2;

    unsigned long long w2[2][8];
    float wb0, wb1;
    {
        const float4* wrow0 = (const float4*)(wp_w + (size_t)d0 * PP);
        const float4* wrow1 = (const float4*)(wp_w + (size_t)(d0 + 1) * PP);
#pragma unroll
        for (int q = 0; q < 4; q++) {
            float4 v0 = wrow0[q], v1 = wrow1[q];
            w2[0][2 * q]     = pack2(v0.x, v0.y);
            w2[0][2 * q + 1] = pack2(v0.z, v0.w);
            w2[1][2 * q]     = pack2(v1.x, v1.y);
            w2[1][2 * q + 1] = pack2(v1.z, v1.w);
        }
        wb0 = wp_b[d0];
        wb1 = wp_b[d0 + 1];
    }

    float* outb = out + ((size_t)(b * 64) * 64 + a) * 256 + d0;

#pragma unroll 2
    for (int n = ng; n < 64; n += 2) {
        const ulonglong2* sv = (const ulonglong2*)&samp[n * 20];
        ulonglong2 v0 = sv[0], v1 = sv[1];
        unsigned long long acc0 = 0ull, acc1 = 0ull;
        acc0 = fma2(v0.x, w2[0][0], acc0);
        acc1 = fma2(v0.x, w2[1][0], acc1);
        acc0 = fma2(v0.y, w2[0][1], acc0);
        acc1 = fma2(v0.y, w2[1][1], acc1);
        acc0 = fma2(v1.x, w2[0][2], acc0);
        acc1 = fma2(v1.x, w2[1][2], acc1);
        acc0 = fma2(v1.y, w2[0][3], acc0);
        acc1 = fma2(v1.y, w2[1][3], acc1);
        ulonglong2 v2 = sv[2], v3 = sv[3];
        acc0 = fma2(v2.x, w2[0][4], acc0);
        acc1 = fma2(v2.x, w2[1][4], acc1);
        acc0 = fma2(v2.y, w2[0][5], acc0);
        acc1 = fma2(v2.y, w2[1][5], acc1);
        acc0 = fma2(v3.x, w2[0][6], acc0);
        acc1 = fma2(v3.x, w2[1][6], acc1);
        acc0 = fma2(v3.y, w2[0][7], acc0);
        acc1 = fma2(v3.y, w2[1][7], acc1);

        float2 a0 = unpack2(acc0);
        float2 a1 = unpack2(acc1);
        float2 r = make_float2(a0.x + a0.y + wb0, a1.x + a1.y + wb1);
        *(float2*)&outb[(size_t)n * (64 * 256)] = r;
    }
}

// ---------------------------------------------------------------------------
extern "C" void kernel_launch(void* const* d_in, const int* in_sizes, int n_in,
                              void* d_out, int out_size)
{
    const float* x      = (const float*)d_in[0];
    const float* conv_w = (const float*)d_in[1];
    const float* conv_b = (const float*)d_in[2];
    const float* lin_w  = (const float*)d_in[3];
    const float* lin_b  = (const float*)d_in[4];
    const float* wp_w   = (const float*)d_in[5];
    const float* wp_b   = (const float*)d_in[6];
    float* out = (float*)d_out;

    k_convpool<<<dim3(NCHUNK, BB), 128>>>(x, conv_w, conv_b);
    k_delta<<<BB, 64>>>(lin_w, lin_b);
    k_main<<<BB * AA, 256>>>(x, wp_w, wp_b, out);
}